// round 2
// baseline (speedup 1.0000x reference)
#include <cuda_runtime.h>
#include <math.h>

#define BATCH  4
#define SEQ    4096
#define DMODEL 1024
#define DH     64

// Projection outputs (scratch) — device globals, no allocation.
__device__ float g_qh[BATCH * SEQ * DH];
__device__ float g_kh[BATCH * SEQ * DH];
__device__ float g_vh[BATCH * SEQ * DH];

// XOR swizzle: keeps 16B-aligned float4 groups intact, spreads banks so that
// transposed scalar stores are only 2-way conflicted and microkernel LDS.128
// reads are conflict-free.
__device__ __forceinline__ int swz4(int kk) { return ((kk >> 2) & 7) << 2; }

// ---------------------------------------------------------------------------
// Fused q/k/v projection: out[row][h] = sum_d x[row][d] * W[h][d] + b[h]
// One block = 64 rows x 64 heads, K chunked by 64. blockIdx.y selects tensor.
// ---------------------------------------------------------------------------
__global__ __launch_bounds__(256)
void proj_kernel(const float* __restrict__ qin, const float* __restrict__ kin,
                 const float* __restrict__ vin,
                 const float* __restrict__ wq, const float* __restrict__ bq,
                 const float* __restrict__ wk, const float* __restrict__ bk,
                 const float* __restrict__ wv, const float* __restrict__ bv)
{
    __shared__ float Xs[64 * 64];  // transposed: Xs[d][row]
    __shared__ float Ws[64 * 64];  // transposed: Ws[d][h]

    const int which = blockIdx.y;
    const float* __restrict__ x    = (which == 0) ? qin : (which == 1) ? kin : vin;
    const float* __restrict__ w    = (which == 0) ? wq  : (which == 1) ? wk  : wv;
    const float* __restrict__ bias = (which == 0) ? bq  : (which == 1) ? bk  : bv;
    float* __restrict__ out        = (which == 0) ? g_qh : (which == 1) ? g_kh : g_vh;

    const int tid = threadIdx.x;
    const int ty = tid >> 4;      // 0..15 : row group
    const int tx = tid & 15;      // 0..15 : col group
    const int row0 = blockIdx.x * 64;

    float acc[4][4] = {};

    for (int kb = 0; kb < DMODEL; kb += 64) {
        __syncthreads();  // previous chunk reads done before overwrite
        #pragma unroll
        for (int it = 0; it < 4; it++) {
            const int f = it * 256 + tid;
            const int r = f >> 4;            // 0..63
            const int c = (f & 15) << 2;     // 0..60 step 4
            const int sw = swz4(c);
            float4 vx = *(const float4*)(x + (size_t)(row0 + r) * DMODEL + kb + c);
            Xs[(c + 0) * 64 + (r ^ sw)] = vx.x;
            Xs[(c + 1) * 64 + (r ^ sw)] = vx.y;
            Xs[(c + 2) * 64 + (r ^ sw)] = vx.z;
            Xs[(c + 3) * 64 + (r ^ sw)] = vx.w;
            float4 vw = *(const float4*)(w + (size_t)r * DMODEL + kb + c);
            Ws[(c + 0) * 64 + (r ^ sw)] = vw.x;
            Ws[(c + 1) * 64 + (r ^ sw)] = vw.y;
            Ws[(c + 2) * 64 + (r ^ sw)] = vw.z;
            Ws[(c + 3) * 64 + (r ^ sw)] = vw.w;
        }
        __syncthreads();

        #pragma unroll 8
        for (int kk = 0; kk < 64; kk++) {
            const int sw = swz4(kk);
            float4 a = *(const float4*)(Xs + kk * 64 + (((ty << 2)) ^ sw));
            float4 b = *(const float4*)(Ws + kk * 64 + (((tx << 2)) ^ sw));
            float av[4] = {a.x, a.y, a.z, a.w};
            float bw[4] = {b.x, b.y, b.z, b.w};
            #pragma unroll
            for (int i = 0; i < 4; i++)
                #pragma unroll
                for (int j = 0; j < 4; j++)
                    acc[i][j] = fmaf(av[i], bw[j], acc[i][j]);
        }
    }

    const int h0 = tx << 2;
    const float b0 = bias[h0 + 0];
    const float b1 = bias[h0 + 1];
    const float b2 = bias[h0 + 2];
    const float b3 = bias[h0 + 3];
    #pragma unroll
    for (int i = 0; i < 4; i++) {
        const size_t orow = (size_t)(row0 + (ty << 2) + i) * DH + h0;
        out[orow + 0] = acc[i][0] + b0;
        out[orow + 1] = acc[i][1] + b1;
        out[orow + 2] = acc[i][2] + b2;
        out[orow + 3] = acc[i][3] + b3;
    }
}

// ---------------------------------------------------------------------------
// Causal flash attention, fp32, Tq = Tk = 64, d_head = 64.
// One block per (batch, q-tile), launched longest-first for balance.
// P tile reuses the K smem buffer -> exactly 48KB static smem.
// ---------------------------------------------------------------------------
__global__ __launch_bounds__(256)
void attn_kernel(float* __restrict__ out)
{
    __shared__ float Qs[64 * 64];  // transposed: Qs[d][q]
    __shared__ float Ks[64 * 64];  // transposed Ks[d][k]; reused as Ps[k][q]
    __shared__ float Vs[64 * 64];  // natural:   Vs[k][d]

    const int tid = threadIdx.x;
    const int ty = tid >> 4;
    const int tx = tid & 15;
    const int b  = blockIdx.x & 3;
    const int qt = 63 - (blockIdx.x >> 2);   // longest blocks scheduled first
    const int q0 = qt * 64;

    const float* __restrict__ qh = g_qh + (size_t)b * SEQ * DH;
    const float* __restrict__ kh = g_kh + (size_t)b * SEQ * DH;
    const float* __restrict__ vh = g_vh + (size_t)b * SEQ * DH;

    // Load Q tile transposed (once)
    #pragma unroll
    for (int it = 0; it < 4; it++) {
        const int f = it * 256 + tid;
        const int r = f >> 4;
        const int c = (f & 15) << 2;
        const int sw = swz4(c);
        float4 v = *(const float4*)(qh + (size_t)(q0 + r) * DH + c);
        Qs[(c + 0) * 64 + (r ^ sw)] = v.x;
        Qs[(c + 1) * 64 + (r ^ sw)] = v.y;
        Qs[(c + 2) * 64 + (r ^ sw)] = v.z;
        Qs[(c + 3) * 64 + (r ^ sw)] = v.w;
    }

    float o[4][4] = {};
    float m[4] = {-3.0e38f, -3.0e38f, -3.0e38f, -3.0e38f};
    float l[4] = {};

    for (int kt = 0; kt <= qt; kt++) {
        const int k0 = kt * 64;
        __syncthreads();  // previous P/V reads done before overwrite
        #pragma unroll
        for (int it = 0; it < 4; it++) {
            const int f = it * 256 + tid;
            const int r = f >> 4;
            const int c = (f & 15) << 2;
            const int sw = swz4(c);
            float4 kv = *(const float4*)(kh + (size_t)(k0 + r) * DH + c);
            Ks[(c + 0) * 64 + (r ^ sw)] = kv.x;
            Ks[(c + 1) * 64 + (r ^ sw)] = kv.y;
            Ks[(c + 2) * 64 + (r ^ sw)] = kv.z;
            Ks[(c + 3) * 64 + (r ^ sw)] = kv.w;
            float4 vv = *(const float4*)(vh + (size_t)(k0 + r) * DH + c);
            *(float4*)(Vs + r * 64 + c) = vv;
        }
        __syncthreads();

        // S = Q K^T  (4x4 register tile per thread)
        float s[4][4] = {};
        #pragma unroll 8
        for (int kk = 0; kk < 64; kk++) {
            const int sw = swz4(kk);
            float4 a = *(const float4*)(Qs + kk * 64 + (((ty << 2)) ^ sw));
            float4 bk4 = *(const float4*)(Ks + kk * 64 + (((tx << 2)) ^ sw));
            float av[4] = {a.x, a.y, a.z, a.w};
            float bw[4] = {bk4.x, bk4.y, bk4.z, bk4.w};
            #pragma unroll
            for (int i = 0; i < 4; i++)
                #pragma unroll
                for (int j = 0; j < 4; j++)
                    s[i][j] = fmaf(av[i], bw[j], s[i][j]);
        }

        // scale + causal mask (only diagonal tile can mask)
        if (kt == qt) {
            #pragma unroll
            for (int i = 0; i < 4; i++)
                #pragma unroll
                for (int j = 0; j < 4; j++) {
                    const bool masked = (k0 + (tx << 2) + j) > (q0 + (ty << 2) + i);
                    s[i][j] = masked ? -1.0e30f : s[i][j] * 0.125f;
                }
        } else {
            #pragma unroll
            for (int i = 0; i < 4; i++)
                #pragma unroll
                for (int j = 0; j < 4; j++)
                    s[i][j] *= 0.125f;
        }

        // online softmax: row-max reduced across the 16-thread row group
        #pragma unroll
        for (int i = 0; i < 4; i++) {
            float r = fmaxf(fmaxf(s[i][0], s[i][1]), fmaxf(s[i][2], s[i][3]));
            r = fmaxf(r, __shfl_xor_sync(0xffffffffu, r, 8));
            r = fmaxf(r, __shfl_xor_sync(0xffffffffu, r, 4));
            r = fmaxf(r, __shfl_xor_sync(0xffffffffu, r, 2));
            r = fmaxf(r, __shfl_xor_sync(0xffffffffu, r, 1));
            const float mn = fmaxf(m[i], r);
            const float alpha = __expf(m[i] - mn);
            m[i] = mn;
            #pragma unroll
            for (int j = 0; j < 4; j++)
                s[i][j] = __expf(s[i][j] - mn);
            l[i] = l[i] * alpha + (s[i][0] + s[i][1] + s[i][2] + s[i][3]);
            #pragma unroll
            for (int j = 0; j < 4; j++)
                o[i][j] *= alpha;
        }

        __syncthreads();  // everyone done reading Ks (scores) before P store
        // P -> Ks buffer, transposed [k][q]
        #pragma unroll
        for (int j = 0; j < 4; j++) {
            const int kcol = (tx << 2) + j;
            const int sw = swz4(kcol);
            #pragma unroll
            for (int i = 0; i < 4; i++)
                Ks[kcol * 64 + (((ty << 2) + i) ^ sw)] = s[i][j];
        }
        __syncthreads();

        // O += P @ V
        #pragma unroll 8
        for (int kk = 0; kk < 64; kk++) {
            const int sw = swz4(kk);
            float4 a = *(const float4*)(Ks + kk * 64 + (((ty << 2)) ^ sw));
            float4 bv4 = *(const float4*)(Vs + kk * 64 + (tx << 2));
            float av[4] = {a.x, a.y, a.z, a.w};
            float bw[4] = {bv4.x, bv4.y, bv4.z, bv4.w};
            #pragma unroll
            for (int i = 0; i < 4; i++)
                #pragma unroll
                for (int j = 0; j < 4; j++)
                    o[i][j] = fmaf(av[i], bw[j], o[i][j]);
        }
    }

    // finalize: reduce partial row sums l across the 16-thread group, divide
    #pragma unroll
    for (int i = 0; i < 4; i++) {
        float li = l[i];
        li += __shfl_xor_sync(0xffffffffu, li, 8);
        li += __shfl_xor_sync(0xffffffffu, li, 4);
        li += __shfl_xor_sync(0xffffffffu, li, 2);
        li += __shfl_xor_sync(0xffffffffu, li, 1);
        const float inv = 1.0f / li;
        const size_t orow = ((size_t)b * SEQ + q0 + (ty << 2) + i) * DH + (tx << 2);
        #pragma unroll
        for (int j = 0; j < 4; j++)
            out[orow + j] = o[i][j] * inv;
    }
}

// ---------------------------------------------------------------------------
extern "C" void kernel_launch(void* const* d_in, const int* in_sizes, int n_in,
                              void* d_out, int out_size)
{
    (void)in_sizes; (void)n_in; (void)out_size;
    const float* q  = (const float*)d_in[0];
    const float* k  = (const float*)d_in[1];
    const float* v  = (const float*)d_in[2];
    const float* wq = (const float*)d_in[3];
    const float* bq = (const float*)d_in[4];
    const float* wk = (const float*)d_in[5];
    const float* bk = (const float*)d_in[6];
    const float* wv = (const float*)d_in[7];
    const float* bv = (const float*)d_in[8];
    float* out = (float*)d_out;

    dim3 pgrid(BATCH * SEQ / 64, 3);   // (256, 3)
    proj_kernel<<<pgrid, 256>>>(q, k, v, wq, bq, wk, bk, wv, bv);
    attn_kernel<<<BATCH * SEQ / 64, 256>>>(out);
}

// round 3
// speedup vs baseline: 1.5858x; 1.5858x over previous
#include <cuda_runtime.h>
#include <math.h>

#define BATCH  4
#define SEQ    4096
#define DMODEL 1024
#define DH     64
#define NCHUNK 8            // max chunks per q-tile (64 k-tiles / 8 per chunk)
#define ATTN_BLOCKS 1152    // 4 batches * 288 (sum over qt of qt/8+1)

// Projection outputs (scratch) — device globals, no allocation.
__device__ float g_qh[BATCH * SEQ * DH];
__device__ float g_kh[BATCH * SEQ * DH];
__device__ float g_vh[BATCH * SEQ * DH];

// Split-KV partials: unnormalized O, row max m, row sum l per chunk.
__device__ float g_po[NCHUNK][BATCH * SEQ * DH];   // 33.5 MB
__device__ float g_pm[NCHUNK][BATCH * SEQ];
__device__ float g_pl[NCHUNK][BATCH * SEQ];

// XOR swizzle on 4-float groups: conflict-free microkernel LDS.128,
// 2-way-max conflicted transpose stores.
__device__ __forceinline__ int swz4(int kk) { return ((kk >> 2) & 7) << 2; }

// ---------------------------------------------------------------------------
// Fused q/k/v projection: out[row][h] = sum_d x[row][d] * W[h][d] + b[h]
// ---------------------------------------------------------------------------
__global__ __launch_bounds__(256)
void proj_kernel(const float* __restrict__ qin, const float* __restrict__ kin,
                 const float* __restrict__ vin,
                 const float* __restrict__ wq, const float* __restrict__ bq,
                 const float* __restrict__ wk, const float* __restrict__ bk,
                 const float* __restrict__ wv, const float* __restrict__ bv)
{
    __shared__ float Xs[64 * 64];  // transposed: Xs[d][row]
    __shared__ float Ws[64 * 64];  // transposed: Ws[d][h]

    const int which = blockIdx.y;
    const float* __restrict__ x    = (which == 0) ? qin : (which == 1) ? kin : vin;
    const float* __restrict__ w    = (which == 0) ? wq  : (which == 1) ? wk  : wv;
    const float* __restrict__ bias = (which == 0) ? bq  : (which == 1) ? bk  : bv;
    float* __restrict__ out        = (which == 0) ? g_qh : (which == 1) ? g_kh : g_vh;

    const int tid = threadIdx.x;
    const int ty = tid >> 4;
    const int tx = tid & 15;
    const int row0 = blockIdx.x * 64;

    float acc[4][4] = {};

    for (int kb = 0; kb < DMODEL; kb += 64) {
        __syncthreads();
        #pragma unroll
        for (int it = 0; it < 4; it++) {
            const int f = it * 256 + tid;
            const int r = f >> 4;
            const int c = (f & 15) << 2;
            const int sw = swz4(c);
            float4 vx = *(const float4*)(x + (size_t)(row0 + r) * DMODEL + kb + c);
            Xs[(c + 0) * 64 + (r ^ sw)] = vx.x;
            Xs[(c + 1) * 64 + (r ^ sw)] = vx.y;
            Xs[(c + 2) * 64 + (r ^ sw)] = vx.z;
            Xs[(c + 3) * 64 + (r ^ sw)] = vx.w;
            float4 vw = *(const float4*)(w + (size_t)r * DMODEL + kb + c);
            Ws[(c + 0) * 64 + (r ^ sw)] = vw.x;
            Ws[(c + 1) * 64 + (r ^ sw)] = vw.y;
            Ws[(c + 2) * 64 + (r ^ sw)] = vw.z;
            Ws[(c + 3) * 64 + (r ^ sw)] = vw.w;
        }
        __syncthreads();

        #pragma unroll   // FULL unroll: swizzle + row offsets fold to immediates
        for (int kk = 0; kk < 64; kk++) {
            const int sw = swz4(kk);
            float4 a = *(const float4*)(Xs + kk * 64 + ((ty << 2) ^ sw));
            float4 b = *(const float4*)(Ws + kk * 64 + ((tx << 2) ^ sw));
            float av[4] = {a.x, a.y, a.z, a.w};
            float bw[4] = {b.x, b.y, b.z, b.w};
            #pragma unroll
            for (int i = 0; i < 4; i++)
                #pragma unroll
                for (int j = 0; j < 4; j++)
                    acc[i][j] = fmaf(av[i], bw[j], acc[i][j]);
        }
    }

    const int h0 = tx << 2;
    const float b0 = bias[h0 + 0];
    const float b1 = bias[h0 + 1];
    const float b2 = bias[h0 + 2];
    const float b3 = bias[h0 + 3];
    #pragma unroll
    for (int i = 0; i < 4; i++) {
        const size_t orow = (size_t)(row0 + (ty << 2) + i) * DH + h0;
        out[orow + 0] = acc[i][0] + b0;
        out[orow + 1] = acc[i][1] + b1;
        out[orow + 2] = acc[i][2] + b2;
        out[orow + 3] = acc[i][3] + b3;
    }
}

// ---------------------------------------------------------------------------
// Causal flash attention with split-KV: one block = (batch, q-tile, 512-key
// chunk). Writes unnormalized partials (o, m, l). 1152 near-uniform blocks.
// ---------------------------------------------------------------------------
__global__ __launch_bounds__(256, 3)
void attn_kernel()
{
    __shared__ float Qs[64 * 64];  // transposed: Qs[d][q]
    __shared__ float Ks[64 * 64];  // transposed Ks[d][k]; reused as Ps[k][q]
    __shared__ float Vs[64 * 64];  // natural:   Vs[k][d]

    const int tid = threadIdx.x;
    const int ty = tid >> 4;
    const int tx = tid & 15;

    // Reverse launch order: long chunks first.
    const int gid = (ATTN_BLOCKS - 1) - blockIdx.x;
    const int b   = gid / 288;
    const int r   = gid - b * 288;
    int a = 0;
    #pragma unroll
    for (int t = 1; t < 8; t++)
        if (4 * t * (t + 1) <= r) a = t;       // octave: qt in [8a, 8a+8)
    const int rr = r - 4 * a * (a + 1);
    const int qt = 8 * a + rr / (a + 1);
    const int c  = rr - (rr / (a + 1)) * (a + 1);   // chunk index, 0..qt/8

    const int q0  = qt * 64;
    const int kt0 = c * 8;
    const int kt1 = min(kt0 + 7, qt);

    const float* __restrict__ qh = g_qh + (size_t)b * SEQ * DH;
    const float* __restrict__ kh = g_kh + (size_t)b * SEQ * DH;
    const float* __restrict__ vh = g_vh + (size_t)b * SEQ * DH;

    // Load Q tile transposed (once)
    #pragma unroll
    for (int it = 0; it < 4; it++) {
        const int f = it * 256 + tid;
        const int rq = f >> 4;
        const int cc = (f & 15) << 2;
        const int sw = swz4(cc);
        float4 v = *(const float4*)(qh + (size_t)(q0 + rq) * DH + cc);
        Qs[(cc + 0) * 64 + (rq ^ sw)] = v.x;
        Qs[(cc + 1) * 64 + (rq ^ sw)] = v.y;
        Qs[(cc + 2) * 64 + (rq ^ sw)] = v.z;
        Qs[(cc + 3) * 64 + (rq ^ sw)] = v.w;
    }

    float o[4][4] = {};
    float m[4] = {-3.0e38f, -3.0e38f, -3.0e38f, -3.0e38f};
    float l[4] = {};

    for (int kt = kt0; kt <= kt1; kt++) {
        const int k0 = kt * 64;
        __syncthreads();
        #pragma unroll
        for (int it = 0; it < 4; it++) {
            const int f = it * 256 + tid;
            const int rk = f >> 4;
            const int cc = (f & 15) << 2;
            const int sw = swz4(cc);
            float4 kv = *(const float4*)(kh + (size_t)(k0 + rk) * DH + cc);
            Ks[(cc + 0) * 64 + (rk ^ sw)] = kv.x;
            Ks[(cc + 1) * 64 + (rk ^ sw)] = kv.y;
            Ks[(cc + 2) * 64 + (rk ^ sw)] = kv.z;
            Ks[(cc + 3) * 64 + (rk ^ sw)] = kv.w;
            float4 vv = *(const float4*)(vh + (size_t)(k0 + rk) * DH + cc);
            *(float4*)(Vs + rk * 64 + cc) = vv;
        }
        __syncthreads();

        // S = Q K^T
        float s[4][4] = {};
        #pragma unroll   // FULL unroll: addresses fold to base + immediate
        for (int kk = 0; kk < 64; kk++) {
            const int sw = swz4(kk);
            float4 aa = *(const float4*)(Qs + kk * 64 + ((ty << 2) ^ sw));
            float4 bk4 = *(const float4*)(Ks + kk * 64 + ((tx << 2) ^ sw));
            float av[4] = {aa.x, aa.y, aa.z, aa.w};
            float bw[4] = {bk4.x, bk4.y, bk4.z, bk4.w};
            #pragma unroll
            for (int i = 0; i < 4; i++)
                #pragma unroll
                for (int j = 0; j < 4; j++)
                    s[i][j] = fmaf(av[i], bw[j], s[i][j]);
        }

        // scale + causal mask (only the diagonal k-tile masks)
        if (kt == qt) {
            #pragma unroll
            for (int i = 0; i < 4; i++)
                #pragma unroll
                for (int j = 0; j < 4; j++) {
                    const bool masked = (k0 + (tx << 2) + j) > (q0 + (ty << 2) + i);
                    s[i][j] = masked ? -1.0e30f : s[i][j] * 0.125f;
                }
        } else {
            #pragma unroll
            for (int i = 0; i < 4; i++)
                #pragma unroll
                for (int j = 0; j < 4; j++)
                    s[i][j] *= 0.125f;
        }

        // online softmax within the chunk
        #pragma unroll
        for (int i = 0; i < 4; i++) {
            float rmax = fmaxf(fmaxf(s[i][0], s[i][1]), fmaxf(s[i][2], s[i][3]));
            rmax = fmaxf(rmax, __shfl_xor_sync(0xffffffffu, rmax, 8));
            rmax = fmaxf(rmax, __shfl_xor_sync(0xffffffffu, rmax, 4));
            rmax = fmaxf(rmax, __shfl_xor_sync(0xffffffffu, rmax, 2));
            rmax = fmaxf(rmax, __shfl_xor_sync(0xffffffffu, rmax, 1));
            const float mn = fmaxf(m[i], rmax);
            const float alpha = __expf(m[i] - mn);
            m[i] = mn;
            #pragma unroll
            for (int j = 0; j < 4; j++)
                s[i][j] = __expf(s[i][j] - mn);
            l[i] = l[i] * alpha + (s[i][0] + s[i][1] + s[i][2] + s[i][3]);
            #pragma unroll
            for (int j = 0; j < 4; j++)
                o[i][j] *= alpha;
        }

        __syncthreads();
        // P -> Ks buffer, transposed [k][q]
        #pragma unroll
        for (int j = 0; j < 4; j++) {
            const int kcol = (tx << 2) + j;
            const int sw = swz4(kcol);
            #pragma unroll
            for (int i = 0; i < 4; i++)
                Ks[kcol * 64 + (((ty << 2) + i) ^ sw)] = s[i][j];
        }
        __syncthreads();

        // O += P @ V
        #pragma unroll   // FULL unroll
        for (int kk = 0; kk < 64; kk++) {
            const int sw = swz4(kk);
            float4 aa = *(const float4*)(Ks + kk * 64 + ((ty << 2) ^ sw));
            float4 bv4 = *(const float4*)(Vs + kk * 64 + (tx << 2));
            float av[4] = {aa.x, aa.y, aa.z, aa.w};
            float bw[4] = {bv4.x, bv4.y, bv4.z, bv4.w};
            #pragma unroll
            for (int i = 0; i < 4; i++)
                #pragma unroll
                for (int j = 0; j < 4; j++)
                    o[i][j] = fmaf(av[i], bw[j], o[i][j]);
        }
    }

    // Write partials: unnormalized o, row max m, reduced row sum l.
    #pragma unroll
    for (int i = 0; i < 4; i++) {
        float li = l[i];
        li += __shfl_xor_sync(0xffffffffu, li, 8);
        li += __shfl_xor_sync(0xffffffffu, li, 4);
        li += __shfl_xor_sync(0xffffffffu, li, 2);
        li += __shfl_xor_sync(0xffffffffu, li, 1);
        const int row = b * SEQ + q0 + (ty << 2) + i;
        *(float4*)&g_po[c][(size_t)row * DH + (tx << 2)] =
            make_float4(o[i][0], o[i][1], o[i][2], o[i][3]);
        if (tx == 0) {
            g_pm[c][row] = m[i];
            g_pl[c][row] = li;
        }
    }
}

// ---------------------------------------------------------------------------
// Merge split-KV partials: out = sum_c exp(m_c-m*) o_c / sum_c exp(m_c-m*) l_c
// One thread per (row, 4-float column group).
// ---------------------------------------------------------------------------
__global__ __launch_bounds__(256)
void merge_kernel(float* __restrict__ out)
{
    const int t = blockIdx.x * 256 + threadIdx.x;   // 16384 * 16 threads
    const int row = t >> 4;
    const int cg  = (t & 15) << 2;
    const int q   = row & (SEQ - 1);
    const int nc  = ((q >> 6) >> 3) + 1;            // chunks for this q-tile

    float mstar = -3.0e38f;
    #pragma unroll 4
    for (int c = 0; c < nc; c++)
        mstar = fmaxf(mstar, g_pm[c][row]);

    float L = 0.0f;
    float4 acc = make_float4(0.f, 0.f, 0.f, 0.f);
    #pragma unroll 4
    for (int c = 0; c < nc; c++) {
        const float w = __expf(g_pm[c][row] - mstar);
        L += w * g_pl[c][row];
        float4 ov = *(const float4*)&g_po[c][(size_t)row * DH + cg];
        acc.x += w * ov.x; acc.y += w * ov.y;
        acc.z += w * ov.z; acc.w += w * ov.w;
    }
    const float inv = 1.0f / L;
    *(float4*)(out + (size_t)row * DH + cg) =
        make_float4(acc.x * inv, acc.y * inv, acc.z * inv, acc.w * inv);
}

// ---------------------------------------------------------------------------
extern "C" void kernel_launch(void* const* d_in, const int* in_sizes, int n_in,
                              void* d_out, int out_size)
{
    (void)in_sizes; (void)n_in; (void)out_size;
    const float* q  = (const float*)d_in[0];
    const float* k  = (const float*)d_in[1];
    const float* v  = (const float*)d_in[2];
    const float* wq = (const float*)d_in[3];
    const float* bq = (const float*)d_in[4];
    const float* wk = (const float*)d_in[5];
    const float* bk = (const float*)d_in[6];
    const float* wv = (const float*)d_in[7];
    const float* bv = (const float*)d_in[8];
    float* out = (float*)d_out;

    dim3 pgrid(BATCH * SEQ / 64, 3);
    proj_kernel<<<pgrid, 256>>>(q, k, v, wq, bq, wk, bk, wv, bv);
    attn_kernel<<<ATTN_BLOCKS, 256>>>();
    merge_kernel<<<BATCH * SEQ * 16 / 256, 256>>>(out);
}